// round 16
// baseline (speedup 1.0000x reference)
#include <cuda_runtime.h>
#include <cuda_fp16.h>

typedef unsigned long long u64;
typedef unsigned int u32;

static constexpr int Bb = 16;
static constexpr int CE = 1024;
static constexpr int Tt = 2048;
static constexpr int CC = 64;
static constexpr int Kk = 4096;

static constexpr long long O_CODES = 0;
static constexpr long long O_QUANT = 32768;
static constexpr long long N_QUANT = (long long)Bb * CE * Tt;    // 33554432
static constexpr long long O_CBL   = O_QUANT + N_QUANT;           // 33587200
static constexpr long long O_CML   = O_CBL + 1;
static constexpr long long O_XPROJ = O_CML + 1;                   // 33587202 (even -> 8B aligned)
static constexpr long long N_XP    = (long long)Bb * CC * Tt;     // 2097152
static constexpr long long O_QPROJ = O_XPROJ + N_XP;              // 35684354 (even)

// scratch (static device globals; no runtime allocation)
__device__ __align__(16) float  g_Win[CC * CE];
__device__ __align__(16) float  g_Wout[CE * CC];
__device__ __align__(16) float  g_cbTr[Kk * CC];     // (-2 * normalized codebook), row-major [k][o]
__device__ __align__(16) float  g_cbn2[Kk];          // ||cb_n||^2
__device__ __align__(16) __half g_cbF16[Kk * CC];    // fp16 of (-2 * cb_n), [k][o]
__device__ __align__(16) float  g_WC[Kk * CE];       // WC[k][o] = cb[k,:] . W_out[o,:]
__device__ double g_lpart[256];

__device__ __forceinline__ u64 pk2(float lo, float hi) {
    u64 r; asm("mov.b64 %0, {%1, %2};" : "=l"(r) : "f"(lo), "f"(hi)); return r;
}
__device__ __forceinline__ void fma2(u64 &d, u64 a, u64 b) {
    asm("fma.rn.f32x2 %0, %1, %2, %0;" : "+l"(d) : "l"(a), "l"(b));
}
__device__ __forceinline__ unsigned s2u(const void* p) {
    return (unsigned)__cvta_generic_to_shared(p);
}
__device__ __forceinline__ void cp16(unsigned s, const void* g) {
    asm volatile("cp.async.cg.shared.global [%0], [%1], 16;" :: "r"(s), "l"(g));
}
__device__ __forceinline__ void cpcommit() { asm volatile("cp.async.commit_group;"); }
__device__ __forceinline__ void cpwait1()  { asm volatile("cp.async.wait_group 1;"); }

// ---- warp-level tensor-core helpers (standard PTX) ----
__device__ __forceinline__ void ldsm4(u32* r, u32 addr) {
    asm volatile("ldmatrix.sync.aligned.m8n8.x4.shared.b16 {%0,%1,%2,%3}, [%4];"
        : "=r"(r[0]), "=r"(r[1]), "=r"(r[2]), "=r"(r[3]) : "r"(addr));
}
__device__ __forceinline__ void ldsm2(u32& r0, u32& r1, u32 addr) {
    asm volatile("ldmatrix.sync.aligned.m8n8.x2.shared.b16 {%0,%1}, [%2];"
        : "=r"(r0), "=r"(r1) : "r"(addr));
}
__device__ __forceinline__ void mma16816h(float* d, const u32* a, const u32* b) {
    asm("mma.sync.aligned.m16n8k16.row.col.f32.f16.f16.f32 "
        "{%0,%1,%2,%3}, {%4,%5,%6,%7}, {%8,%9}, {%0,%1,%2,%3};"
        : "+f"(d[0]), "+f"(d[1]), "+f"(d[2]), "+f"(d[3])
        : "r"(a[0]), "r"(a[1]), "r"(a[2]), "r"(a[3]), "r"(b[0]), "r"(b[1]));
}

// ---------------- prep: weight-norm W_in ----------------
__global__ __launch_bounds__(256) void k_prep_win(const float* __restrict__ v_in,
                                                  const float* __restrict__ g_in)
{
    __shared__ float sb[256];
    __shared__ float snorm;
    int o = blockIdx.x, tid = threadIdx.x;
    float s = 0.f;
#pragma unroll
    for (int j = 0; j < 4; j++) { float v = v_in[o * CE + tid + j * 256]; s += v * v; }
    sb[tid] = s; __syncthreads();
    for (int off = 128; off > 0; off >>= 1) { if (tid < off) sb[tid] += sb[tid + off]; __syncthreads(); }
    if (tid == 0) snorm = __fsqrt_rn(sb[0]);
    __syncthreads();
    float n = snorm, g = g_in[o];
#pragma unroll
    for (int j = 0; j < 4; j++) {
        int i = tid + j * 256;
        g_Win[o * CE + i] = __fdiv_rn(g * v_in[o * CE + i], n);
    }
}

// ---------------- prep: weight-norm W_out ----------------
__global__ __launch_bounds__(256) void k_prep_wout(const float* __restrict__ v_out,
                                                   const float* __restrict__ g_out)
{
    int gw = (blockIdx.x * 256 + threadIdx.x) >> 5;
    int l = threadIdx.x & 31;
    float a = v_out[gw * CC + l], b = v_out[gw * CC + l + 32];
    float s = a * a + b * b;
#pragma unroll
    for (int off = 16; off; off >>= 1) s += __shfl_xor_sync(0xffffffffu, s, off);
    float n = __fsqrt_rn(s), g = g_out[gw];
    g_Wout[gw * CC + l]      = __fdiv_rn(g * a, n);
    g_Wout[gw * CC + l + 32] = __fdiv_rn(g * b, n);
}

// ---------------- prep: codebook -> cbTr (-2x), cbn2, fp16 rows ----------------
__global__ __launch_bounds__(256) void k_prep_cb(const float* __restrict__ cb)
{
    int k = (blockIdx.x * 256 + threadIdx.x) >> 5;
    int l = threadIdx.x & 31;
    float a = cb[k * CC + l], b = cb[k * CC + l + 32];
    float s = a * a + b * b;
#pragma unroll
    for (int off = 16; off; off >>= 1) s += __shfl_xor_sync(0xffffffffu, s, off);
    float n = fmaxf(__fsqrt_rn(s), 1e-12f);
    float ca = __fdiv_rn(a, n), cbv = __fdiv_rn(b, n);
    float v1 = -2.f * ca, v2 = -2.f * cbv;
    g_cbTr[k * CC + l]      = v1;
    g_cbTr[k * CC + l + 32] = v2;
    g_cbF16[k * CC + l]      = __float2half_rn(v1);
    g_cbF16[k * CC + l + 32] = __float2half_rn(v2);
    float s2 = ca * ca + cbv * cbv;
#pragma unroll
    for (int off = 16; off; off >>= 1) s2 += __shfl_xor_sync(0xffffffffu, s2, off);
    if (l == 0) g_cbn2[k] = s2;
}

// ---------------- WC = codebook @ W_out^T ----------------
__global__ __launch_bounds__(256) void k_wc(const float* __restrict__ cb)
{
    __shared__ __align__(16) float CBt[64][68];
    __shared__ __align__(16) float WT[64][132];
    int k0 = blockIdx.x * 64;
    int o0 = blockIdx.y * 128;
    int tid = threadIdx.x;
    int to = tid >> 4, tt = tid & 15;

#pragma unroll
    for (int it = 0; it < 4; it++) {
        int rr = tid + it * 256;
        int code = rr >> 4, q = rr & 15;
        float4 v = *(const float4*)&cb[(long long)(k0 + code) * CC + q * 4];
        CBt[q * 4 + 0][code] = v.x; CBt[q * 4 + 1][code] = v.y;
        CBt[q * 4 + 2][code] = v.z; CBt[q * 4 + 3][code] = v.w;
    }
#pragma unroll
    for (int it = 0; it < 8; it++) {
        int rr = tid + it * 256;
        int o = rr >> 4, q = rr & 15;
        float4 v = *(const float4*)&g_Wout[(long long)(o0 + o) * CC + q * 4];
        WT[q * 4 + 0][o] = v.x; WT[q * 4 + 1][o] = v.y;
        WT[q * 4 + 2][o] = v.z; WT[q * 4 + 3][o] = v.w;
    }
    __syncthreads();

    u64 acc[4][4];
#pragma unroll
    for (int i = 0; i < 4; i++)
#pragma unroll
        for (int j = 0; j < 4; j++) acc[i][j] = 0ull;

#pragma unroll 8
    for (int i = 0; i < 64; i++) {
        float4 w  = *(const float4*)&CBt[i][to * 4];
        float4 xa = *(const float4*)&WT[i][tt * 4];
        float4 xb = *(const float4*)&WT[i][64 + tt * 4];
        u64 xa0 = pk2(xa.x, xa.y), xa1 = pk2(xa.z, xa.w);
        u64 xb0 = pk2(xb.x, xb.y), xb1 = pk2(xb.z, xb.w);
        u64 w0 = pk2(w.x, w.x), w1 = pk2(w.y, w.y), w2 = pk2(w.z, w.z), w3 = pk2(w.w, w.w);
        fma2(acc[0][0], w0, xa0); fma2(acc[0][1], w0, xa1); fma2(acc[0][2], w0, xb0); fma2(acc[0][3], w0, xb1);
        fma2(acc[1][0], w1, xa0); fma2(acc[1][1], w1, xa1); fma2(acc[1][2], w1, xb0); fma2(acc[1][3], w1, xb1);
        fma2(acc[2][0], w2, xa0); fma2(acc[2][1], w2, xa1); fma2(acc[2][2], w2, xb0); fma2(acc[2][3], w2, xb1);
        fma2(acc[3][0], w3, xa0); fma2(acc[3][1], w3, xa1); fma2(acc[3][2], w3, xb0); fma2(acc[3][3], w3, xb1);
    }
#pragma unroll
    for (int oj = 0; oj < 4; oj++) {
        float* row = &g_WC[(long long)(k0 + to * 4 + oj) * CE + o0];
        *(u64*)&row[tt * 4]          = acc[oj][0];
        *(u64*)&row[tt * 4 + 2]      = acc[oj][1];
        *(u64*)&row[64 + tt * 4]     = acc[oj][2];
        *(u64*)&row[64 + tt * 4 + 2] = acc[oj][3];
    }
}

// ---------------- gather: quantized[b,o,t] = WC[code[b,t]][o] ----------------
__global__ __launch_bounds__(256) void k_gather(float* __restrict__ out)
{
    __shared__ __align__(16) float Tile[64 * 132];
    __shared__ int scode[128];
    int b = blockIdx.y, tid = threadIdx.x;
    long long t0 = (long long)blockIdx.x * 128;

    if (tid < 128) scode[tid] = (int)out[O_CODES + (long long)b * Tt + t0 + tid];
    __syncthreads();

    for (int oc = 0; oc < 16; oc++) {
#pragma unroll
        for (int it = 0; it < 8; it++) {
            int rr = tid + it * 256;
            int t = rr >> 4, q = rr & 15;
            float4 v = *(const float4*)&g_WC[(long long)scode[t] * CE + oc * 64 + q * 4];
            Tile[(q * 4 + 0) * 132 + t] = v.x;
            Tile[(q * 4 + 1) * 132 + t] = v.y;
            Tile[(q * 4 + 2) * 132 + t] = v.z;
            Tile[(q * 4 + 3) * 132 + t] = v.w;
        }
        __syncthreads();
#pragma unroll
        for (int it = 0; it < 8; it++) {
            int rr = tid + it * 256;
            int o = rr >> 5, t4 = rr & 31;
            *(float4*)&out[O_QUANT + (long long)b * CE * Tt + (long long)(oc * 64 + o) * Tt + t0 + t4 * 4]
                = *(const float4*)&Tile[o * 132 + t4 * 4];
        }
        __syncthreads();
    }
}

// ---------------- gemm (xproj): Out[64 x 128t] = W[64 x K] @ X[K x 128t] ----------------
__global__ __launch_bounds__(256, 2) void k_gemm64(const float* __restrict__ W, int K,
                                                   const float* __restrict__ X, long long XyS,
                                                   float* __restrict__ O, long long OyS)
{
    __shared__ __align__(16) float Ws[32][68];
    __shared__ __align__(16) float Xs[32][128];
    const float* Xp = X + (long long)blockIdx.y * XyS;
    float* Op = O + (long long)blockIdx.y * OyS + (long long)blockIdx.x * 128;
    int tid = threadIdx.x;
    int to = tid >> 4, tt = tid & 15;
    long long t0 = (long long)blockIdx.x * 128;

    u64 acc[4][4];
#pragma unroll
    for (int i = 0; i < 4; i++)
#pragma unroll
        for (int j = 0; j < 4; j++) acc[i][j] = 0ull;

    for (int kc = 0; kc < K; kc += 32) {
#pragma unroll
        for (int it = 0; it < 2; it++) {
            int rr = tid + it * 256;
            int o = rr >> 3, kq = rr & 7;
            float4 w = *(const float4*)&W[(long long)o * K + kc + kq * 4];
            Ws[kq * 4 + 0][o] = w.x; Ws[kq * 4 + 1][o] = w.y;
            Ws[kq * 4 + 2][o] = w.z; Ws[kq * 4 + 3][o] = w.w;
        }
#pragma unroll
        for (int it = 0; it < 4; it++) {
            int rr = tid + it * 256;
            int i = rr >> 5, t4 = rr & 31;
            *(float4*)&Xs[i][t4 * 4] = *(const float4*)&Xp[(long long)(kc + i) * Tt + t0 + t4 * 4];
        }
        __syncthreads();
        float4 wn  = *(const float4*)&Ws[0][to * 4];
        float4 xan = *(const float4*)&Xs[0][tt * 4];
        float4 xbn = *(const float4*)&Xs[0][64 + tt * 4];
#pragma unroll 8
        for (int k = 0; k < 32; k++) {
            float4 w = wn, xa = xan, xb = xbn;
            if (k < 31) {
                wn  = *(const float4*)&Ws[k + 1][to * 4];
                xan = *(const float4*)&Xs[k + 1][tt * 4];
                xbn = *(const float4*)&Xs[k + 1][64 + tt * 4];
            }
            u64 xa0 = pk2(xa.x, xa.y), xa1 = pk2(xa.z, xa.w);
            u64 xb0 = pk2(xb.x, xb.y), xb1 = pk2(xb.z, xb.w);
            u64 w0 = pk2(w.x, w.x), w1 = pk2(w.y, w.y), w2 = pk2(w.z, w.z), w3 = pk2(w.w, w.w);
            fma2(acc[0][0], w0, xa0); fma2(acc[0][1], w0, xa1); fma2(acc[0][2], w0, xb0); fma2(acc[0][3], w0, xb1);
            fma2(acc[1][0], w1, xa0); fma2(acc[1][1], w1, xa1); fma2(acc[1][2], w1, xb0); fma2(acc[1][3], w1, xb1);
            fma2(acc[2][0], w2, xa0); fma2(acc[2][1], w2, xa1); fma2(acc[2][2], w2, xb0); fma2(acc[2][3], w2, xb1);
            fma2(acc[3][0], w3, xa0); fma2(acc[3][1], w3, xa1); fma2(acc[3][2], w3, xb0); fma2(acc[3][3], w3, xb1);
        }
        __syncthreads();
    }
#pragma unroll
    for (int oj = 0; oj < 4; oj++) {
        long long rb = (long long)(to * 4 + oj) * Tt;
        *(u64*)&Op[rb + tt * 4]          = acc[oj][0];
        *(u64*)&Op[rb + tt * 4 + 2]      = acc[oj][1];
        *(u64*)&Op[rb + 64 + tt * 4]     = acc[oj][2];
        *(u64*)&Op[rb + 64 + tt * 4 + 2] = acc[oj][3];
    }
}

// ---------------- dist v4: fp16 single-term MMA + top-4 window + exact recheck ----------------
// block = 128 t, 4 warps (2 rowsets each); 16 chunks of 256 codes, double-buffered.
// A[t][64] = fp16(e); B[k][64] = fp16(-2*cb_n); acc init = ||cb_n||^2.
// Coarse err ~1e-4 rms; every candidate within 6e-3 of coarse best is re-scored
// exactly in fp32 (ascending-o fmaf, k-tiebreak) -> codes are exact-argmin.
static constexpr int BST = 144;                      // smem row stride (bytes), conflict-free ldmatrix
static constexpr int SM_A  = 0;                      // 128 * 144 = 18432
static constexpr int SM_B  = 18432;                  // 2 stages x 256*144 = 73728
static constexpr int SM_CC = 92160;                  // 2 x 256 floats = 2048
static constexpr int SM_DEN= 94208;                  // 128 floats
static constexpr int SM_SC = 94720;                  // 128 ints
static constexpr int SMEM_DIST = 95232;

__global__ __launch_bounds__(128, 2) void k_dist(const float* __restrict__ cb,
                                                 float* __restrict__ out)
{
    extern __shared__ __align__(1024) char smc[];
    float* ccB  = (float*)(smc + SM_CC);
    float* den  = (float*)(smc + SM_DEN);
    int*   scode= (int*)(smc + SM_SC);
    float* mv   = (float*)(smc + SM_B);              // merge bufs overlap B after loop
    int*   mi   = (int*)(smc + SM_B + 8192);

    int b = blockIdx.y, tid = threadIdx.x;
    int wid = tid >> 5, lane = tid & 31;
    long long t0 = (long long)blockIdx.x * 128;
    const long long xbase = O_XPROJ + (long long)b * (CC * Tt) + t0;

    // ---- stage x_proj (64 o x 128 t) into B region; den; build fp16 A ----
    float* stage = (float*)(smc + SM_B);             // [64][132]
#pragma unroll
    for (int it = 0; it < 32; it++) {
        int rr = tid + it * 128;                     // 4096 u64
        int o = rr >> 6, t2 = rr & 63;
        *(u64*)&stage[o * 132 + t2 * 2] = *(const u64*)&out[xbase + (long long)o * Tt + t2 * 2];
    }
    __syncthreads();
    {
        float s = 0.f;
#pragma unroll 8
        for (int o = 0; o < 64; o++) { float v = stage[o * 132 + tid]; s += v * v; }
        den[tid] = fmaxf(__fsqrt_rn(s), 1e-12f);
    }
    __syncthreads();
#pragma unroll
    for (int it = 0; it < 64; it++) {
        int rr = tid + it * 128;                     // 8192: t = rr>>6, o = rr&63
        int t = rr >> 6, o = rr & 63;
        float e = __fdiv_rn(stage[o * 132 + t], den[t]);
        *(__half*)(smc + SM_A + t * BST + o * 2) = __float2half_rn(e);
    }
    __syncthreads();

    // ---- A fragments: 2 rowsets x 4 ks x 4 regs, resident ----
    u32 afr[2][4][4];
#pragma unroll
    for (int rs = 0; rs < 2; rs++) {
        int row = rs * 64 + wid * 16 + (lane & 15);
        u32 acolb = (u32)((lane >> 4) * 16);
#pragma unroll
        for (int ks = 0; ks < 4; ks++)
            ldsm4(afr[rs][ks], s2u(smc + SM_A + row * BST + ks * 32 + acolb));
    }

    const float FINF = 3.4028235e38f;
    const int IMAX = 0x7fffffff;
    // top-4 lists: [rs][half][4]
    float lv[2][2][4]; int li[2][2][4];
#pragma unroll
    for (int rs = 0; rs < 2; rs++)
#pragma unroll
        for (int h = 0; h < 2; h++)
#pragma unroll
            for (int j = 0; j < 4; j++) { lv[rs][h][j] = FINF; li[rs][h][j] = IMAX; }

    auto loadB = [&](int st, int kc0) {
        char* Bd = smc + SM_B + st * (256 * BST);
        const char* gs = (const char*)g_cbF16 + (long long)kc0 * 128;
#pragma unroll
        for (int it = 0; it < 16; it++) {
            int i = tid + it * 128;                  // 2048 = 256 rows x 8 segs
            int row = i >> 3, seg = i & 7;
            cp16(s2u(Bd + row * BST + seg * 16), gs + row * 128 + seg * 16);
        }
        if (tid < 64) cp16(s2u((char*)(ccB + st * 256) + tid * 16), (const char*)(g_cbn2 + kc0) + tid * 16);
    };

    loadB(0, 0); cpcommit();
    for (int ch = 0; ch < 16; ch++) {
        if (ch + 1 < 16) loadB((ch + 1) & 1, (ch + 1) * 256);
        cpcommit(); cpwait1(); __syncthreads();
        const float* ccs = ccB + (ch & 1) * 256;
        char* Bd = smc + SM_B + (ch & 1) * (256 * BST);
        int kc0 = ch * 256;
        int col = 2 * (lane & 3);
        u32 brow = (u32)(lane & 7);
        u32 bselb = (u32)(((lane >> 3) & 1) * 16);

#pragma unroll
        for (int ntp = 0; ntp < 16; ntp++) {
            int nt = ntp * 2;
            float d[2][2][4];                        // [rs][j][4]
#pragma unroll
            for (int j = 0; j < 2; j++) {
                int n0 = (nt + j) * 8;
                float c0 = ccs[n0 + col], c1 = ccs[n0 + col + 1];
                d[0][j][0] = c0; d[0][j][1] = c1; d[0][j][2] = c0; d[0][j][3] = c1;
                d[1][j][0] = c0; d[1][j][1] = c1; d[1][j][2] = c0; d[1][j][3] = c1;
            }
            u32 bf[4][2][2];
#pragma unroll
            for (int ks = 0; ks < 4; ks++)
#pragma unroll
                for (int j = 0; j < 2; j++)
                    ldsm2(bf[ks][j][0], bf[ks][j][1],
                          s2u(Bd + ((nt + j) * 8 + brow) * BST + ks * 32 + bselb));
#pragma unroll
            for (int ks = 0; ks < 4; ks++) {
                mma16816h(d[0][0], afr[0][ks], bf[ks][0]);
                mma16816h(d[0][1], afr[0][ks], bf[ks][1]);
                mma16816h(d[1][0], afr[1][ks], bf[ks][0]);
                mma16816h(d[1][1], afr[1][ks], bf[ks][1]);
            }
#pragma unroll
            for (int rs = 0; rs < 2; rs++)
#pragma unroll
                for (int j = 0; j < 2; j++) {
                    int kg = kc0 + (nt + j) * 8 + col;
#pragma unroll
                    for (int h = 0; h < 2; h++) {
#pragma unroll
                        for (int p = 0; p < 2; p++) {
                            float v = d[rs][j][h * 2 + p];
                            int kk = kg + p;
                            float* L = lv[rs][h]; int* I = li[rs][h];
                            if (v < L[3]) {
                                if (v < L[1]) {
                                    L[3] = L[2]; I[3] = I[2]; L[2] = L[1]; I[2] = I[1];
                                    if (v < L[0]) { L[1] = L[0]; I[1] = I[0]; L[0] = v; I[0] = kk; }
                                    else          { L[1] = v; I[1] = kk; }
                                } else {
                                    if (v < L[2]) { L[3] = L[2]; I[3] = I[2]; L[2] = v; I[2] = kk; }
                                    else          { L[3] = v; I[3] = kk; }
                                }
                            }
                        }
                    }
                }
        }
        __syncthreads();
    }

    // ---- merge: write per-(row,lane-col) lists, then per-t exact window select ----
#pragma unroll
    for (int rs = 0; rs < 2; rs++)
#pragma unroll
        for (int h = 0; h < 2; h++) {
            int row = rs * 64 + wid * 16 + h * 8 + (lane >> 2);
            int base = row * 16 + (lane & 3) * 4;
#pragma unroll
            for (int j = 0; j < 4; j++) { mv[base + j] = lv[rs][h][j]; mi[base + j] = li[rs][h][j]; }
        }
    __syncthreads();
    {
        int t = tid;
        float v1 = FINF;
#pragma unroll
        for (int e = 0; e < 16; e++) v1 = fminf(v1, mv[t * 16 + e]);
        float thr = v1 + 6e-3f;
        float dn = den[t];
        float bs = FINF; int bk = IMAX;
        for (int e = 0; e < 16; e++) {
            float v = mv[t * 16 + e]; int k = mi[t * 16 + e];
            if (v <= thr && k != IMAX) {
                float s = g_cbn2[k];
                const float* r = g_cbTr + (long long)k * CC;
#pragma unroll 8
                for (int o = 0; o < 64; o++) {
                    float e0 = __fdiv_rn(out[xbase + (long long)o * Tt + t], dn);
                    s = fmaf(r[o], e0, s);
                }
                if (s < bs || (s == bs && k < bk)) { bs = s; bk = k; }
            }
        }
        scode[t] = bk;
        out[O_CODES + (long long)b * Tt + t0 + t] = (float)bk;
    }
    __syncthreads();

    // ---- gather q, write quantized_proj = xp + (q - xp), accumulate loss ----
    {
        int code = scode[tid];
        const float* cbrow = cb + (long long)code * CC;
        long long xb2 = xbase + tid;
        long long qb2 = O_QPROJ + (long long)b * (CC * Tt) + t0 + tid;
        float ls = 0.f;
#pragma unroll 8
        for (int j = 0; j < 64; j++) {
            long long ro = (long long)j * Tt;
            float xp = out[xb2 + ro];
            float qv = cbrow[j];
            float dd = qv - xp;
            out[qb2 + ro] = xp + dd;
            ls += dd * dd;
        }
        __syncthreads();
        mv[tid] = ls; __syncthreads();
        for (int off = 64; off > 0; off >>= 1) {
            if (tid < off) mv[tid] += mv[tid + off];
            __syncthreads();
        }
        if (tid == 0) g_lpart[blockIdx.y * gridDim.x + blockIdx.x] = (double)mv[0];
    }
}

// ---------------- final loss reduction (256 partials) ----------------
__global__ __launch_bounds__(256) void k_loss(float* __restrict__ out)
{
    __shared__ double sb[256];
    int tid = threadIdx.x;
    sb[tid] = g_lpart[tid];
    __syncthreads();
    for (int off = 128; off > 0; off >>= 1) {
        if (tid < off) sb[tid] += sb[tid + off];
        __syncthreads();
    }
    if (tid == 0) {
        float l = (float)(sb[0] / (double)(16.0 * 64.0 * 2048.0));
        out[O_CBL] = l;
        out[O_CML] = l;
    }
}

extern "C" void kernel_launch(void* const* d_in, const int* in_sizes, int n_in,
                              void* d_out, int out_size) {
    (void)in_sizes; (void)n_in; (void)out_size;
    const float* x    = (const float*)d_in[0];
    const float* v_in = (const float*)d_in[1];
    const float* g_in = (const float*)d_in[2];
    const float* v_out= (const float*)d_in[3];
    const float* g_out= (const float*)d_in[4];
    const float* cb   = (const float*)d_in[5];
    float* out = (float*)d_out;

    cudaFuncSetAttribute(k_dist, cudaFuncAttributeMaxDynamicSharedMemorySize, SMEM_DIST);

    k_prep_win<<<64, 256>>>(v_in, g_in);
    k_prep_wout<<<128, 256>>>(v_out, g_out);
    k_prep_cb<<<512, 256>>>(cb);

    float* winp; cudaGetSymbolAddress((void**)&winp, g_Win);

    // WC = codebook @ W_out^T
    k_wc<<<dim3(64, 8), 256>>>(cb);

    // x_proj = W_in @ x
    k_gemm64<<<dim3(16, 16), 256>>>(winp, CE, x, (long long)CE * Tt,
                                    out + O_XPROJ, (long long)CC * Tt);

    // codes / qproj / loss partials (fp16 tensor-core dist, top-4 window recheck)
    k_dist<<<dim3(16, 16), 128, SMEM_DIST>>>(cb, out);
    k_loss<<<1, 256>>>(out);

    // quantized via gather from WC
    k_gather<<<dim3(16, 16), 256>>>(out);
}

// round 17
// speedup vs baseline: 1.6009x; 1.6009x over previous
#include <cuda_runtime.h>
#include <cuda_fp16.h>

typedef unsigned long long u64;
typedef unsigned int u32;

static constexpr int Bb = 16;
static constexpr int CE = 1024;
static constexpr int Tt = 2048;
static constexpr int CC = 64;
static constexpr int Kk = 4096;

static constexpr long long O_CODES = 0;
static constexpr long long O_QUANT = 32768;
static constexpr long long N_QUANT = (long long)Bb * CE * Tt;    // 33554432
static constexpr long long O_CBL   = O_QUANT + N_QUANT;           // 33587200
static constexpr long long O_CML   = O_CBL + 1;
static constexpr long long O_XPROJ = O_CML + 1;                   // 33587202 (even -> 8B aligned)
static constexpr long long N_XP    = (long long)Bb * CC * Tt;     // 2097152
static constexpr long long O_QPROJ = O_XPROJ + N_XP;              // 35684354 (even)

// scratch (static device globals; no runtime allocation)
__device__ __align__(16) float  g_Win[CC * CE];
__device__ __align__(16) float  g_Wout[CE * CC];
__device__ __align__(16) float  g_cbTr[Kk * CC];     // (-2 * normalized codebook), row-major [k][o]
__device__ __align__(16) float  g_cbn2[Kk];          // ||cb_n||^2
__device__ __align__(16) __half g_cbF16[Kk * CC];    // fp16 of (-2 * cb_n), [k][o]
__device__ __align__(16) float  g_WC[Kk * CE];       // WC[k][o] = cb[k,:] . W_out[o,:]
__device__ double g_lpart[128];

__device__ __forceinline__ u64 pk2(float lo, float hi) {
    u64 r; asm("mov.b64 %0, {%1, %2};" : "=l"(r) : "f"(lo), "f"(hi)); return r;
}
__device__ __forceinline__ void fma2(u64 &d, u64 a, u64 b) {
    asm("fma.rn.f32x2 %0, %1, %2, %0;" : "+l"(d) : "l"(a), "l"(b));
}
__device__ __forceinline__ unsigned s2u(const void* p) {
    return (unsigned)__cvta_generic_to_shared(p);
}
__device__ __forceinline__ void cp16(unsigned s, const void* g) {
    asm volatile("cp.async.cg.shared.global [%0], [%1], 16;" :: "r"(s), "l"(g));
}
__device__ __forceinline__ void cpcommit() { asm volatile("cp.async.commit_group;"); }
__device__ __forceinline__ void cpwait1()  { asm volatile("cp.async.wait_group 1;"); }

// ---- warp-level tensor-core helpers (standard PTX) ----
__device__ __forceinline__ void ldsm4(u32* r, u32 addr) {
    asm volatile("ldmatrix.sync.aligned.m8n8.x4.shared.b16 {%0,%1,%2,%3}, [%4];"
        : "=r"(r[0]), "=r"(r[1]), "=r"(r[2]), "=r"(r[3]) : "r"(addr));
}
__device__ __forceinline__ void ldsm2(u32& r0, u32& r1, u32 addr) {
    asm volatile("ldmatrix.sync.aligned.m8n8.x2.shared.b16 {%0,%1}, [%2];"
        : "=r"(r0), "=r"(r1) : "r"(addr));
}
__device__ __forceinline__ void mma16816h(float* d, const u32* a, const u32* b) {
    asm("mma.sync.aligned.m16n8k16.row.col.f32.f16.f16.f32 "
        "{%0,%1,%2,%3}, {%4,%5,%6,%7}, {%8,%9}, {%0,%1,%2,%3};"
        : "+f"(d[0]), "+f"(d[1]), "+f"(d[2]), "+f"(d[3])
        : "r"(a[0]), "r"(a[1]), "r"(a[2]), "r"(a[3]), "r"(b[0]), "r"(b[1]));
}

// ---------------- prep: weight-norm W_in ----------------
__global__ __launch_bounds__(256) void k_prep_win(const float* __restrict__ v_in,
                                                  const float* __restrict__ g_in)
{
    __shared__ float sb[256];
    __shared__ float snorm;
    int o = blockIdx.x, tid = threadIdx.x;
    float s = 0.f;
#pragma unroll
    for (int j = 0; j < 4; j++) { float v = v_in[o * CE + tid + j * 256]; s += v * v; }
    sb[tid] = s; __syncthreads();
    for (int off = 128; off > 0; off >>= 1) { if (tid < off) sb[tid] += sb[tid + off]; __syncthreads(); }
    if (tid == 0) snorm = __fsqrt_rn(sb[0]);
    __syncthreads();
    float n = snorm, g = g_in[o];
#pragma unroll
    for (int j = 0; j < 4; j++) {
        int i = tid + j * 256;
        g_Win[o * CE + i] = __fdiv_rn(g * v_in[o * CE + i], n);
    }
}

// ---------------- prep: weight-norm W_out ----------------
__global__ __launch_bounds__(256) void k_prep_wout(const float* __restrict__ v_out,
                                                   const float* __restrict__ g_out)
{
    int gw = (blockIdx.x * 256 + threadIdx.x) >> 5;
    int l = threadIdx.x & 31;
    float a = v_out[gw * CC + l], b = v_out[gw * CC + l + 32];
    float s = a * a + b * b;
#pragma unroll
    for (int off = 16; off; off >>= 1) s += __shfl_xor_sync(0xffffffffu, s, off);
    float n = __fsqrt_rn(s), g = g_out[gw];
    g_Wout[gw * CC + l]      = __fdiv_rn(g * a, n);
    g_Wout[gw * CC + l + 32] = __fdiv_rn(g * b, n);
}

// ---------------- prep: codebook -> cbTr (-2x), cbn2, fp16 rows ----------------
__global__ __launch_bounds__(256) void k_prep_cb(const float* __restrict__ cb)
{
    int k = (blockIdx.x * 256 + threadIdx.x) >> 5;
    int l = threadIdx.x & 31;
    float a = cb[k * CC + l], b = cb[k * CC + l + 32];
    float s = a * a + b * b;
#pragma unroll
    for (int off = 16; off; off >>= 1) s += __shfl_xor_sync(0xffffffffu, s, off);
    float n = fmaxf(__fsqrt_rn(s), 1e-12f);
    float ca = __fdiv_rn(a, n), cbv = __fdiv_rn(b, n);
    float v1 = -2.f * ca, v2 = -2.f * cbv;
    g_cbTr[k * CC + l]      = v1;
    g_cbTr[k * CC + l + 32] = v2;
    g_cbF16[k * CC + l]      = __float2half_rn(v1);
    g_cbF16[k * CC + l + 32] = __float2half_rn(v2);
    float s2 = ca * ca + cbv * cbv;
#pragma unroll
    for (int off = 16; off; off >>= 1) s2 += __shfl_xor_sync(0xffffffffu, s2, off);
    if (l == 0) g_cbn2[k] = s2;
}

// ---------------- WC = codebook @ W_out^T ----------------
__global__ __launch_bounds__(256) void k_wc(const float* __restrict__ cb)
{
    __shared__ __align__(16) float CBt[64][68];
    __shared__ __align__(16) float WT[64][132];
    int k0 = blockIdx.x * 64;
    int o0 = blockIdx.y * 128;
    int tid = threadIdx.x;
    int to = tid >> 4, tt = tid & 15;

#pragma unroll
    for (int it = 0; it < 4; it++) {
        int rr = tid + it * 256;
        int code = rr >> 4, q = rr & 15;
        float4 v = *(const float4*)&cb[(long long)(k0 + code) * CC + q * 4];
        CBt[q * 4 + 0][code] = v.x; CBt[q * 4 + 1][code] = v.y;
        CBt[q * 4 + 2][code] = v.z; CBt[q * 4 + 3][code] = v.w;
    }
#pragma unroll
    for (int it = 0; it < 8; it++) {
        int rr = tid + it * 256;
        int o = rr >> 4, q = rr & 15;
        float4 v = *(const float4*)&g_Wout[(long long)(o0 + o) * CC + q * 4];
        WT[q * 4 + 0][o] = v.x; WT[q * 4 + 1][o] = v.y;
        WT[q * 4 + 2][o] = v.z; WT[q * 4 + 3][o] = v.w;
    }
    __syncthreads();

    u64 acc[4][4];
#pragma unroll
    for (int i = 0; i < 4; i++)
#pragma unroll
        for (int j = 0; j < 4; j++) acc[i][j] = 0ull;

#pragma unroll 8
    for (int i = 0; i < 64; i++) {
        float4 w  = *(const float4*)&CBt[i][to * 4];
        float4 xa = *(const float4*)&WT[i][tt * 4];
        float4 xb = *(const float4*)&WT[i][64 + tt * 4];
        u64 xa0 = pk2(xa.x, xa.y), xa1 = pk2(xa.z, xa.w);
        u64 xb0 = pk2(xb.x, xb.y), xb1 = pk2(xb.z, xb.w);
        u64 w0 = pk2(w.x, w.x), w1 = pk2(w.y, w.y), w2 = pk2(w.z, w.z), w3 = pk2(w.w, w.w);
        fma2(acc[0][0], w0, xa0); fma2(acc[0][1], w0, xa1); fma2(acc[0][2], w0, xb0); fma2(acc[0][3], w0, xb1);
        fma2(acc[1][0], w1, xa0); fma2(acc[1][1], w1, xa1); fma2(acc[1][2], w1, xb0); fma2(acc[1][3], w1, xb1);
        fma2(acc[2][0], w2, xa0); fma2(acc[2][1], w2, xa1); fma2(acc[2][2], w2, xb0); fma2(acc[2][3], w2, xb1);
        fma2(acc[3][0], w3, xa0); fma2(acc[3][1], w3, xa1); fma2(acc[3][2], w3, xb0); fma2(acc[3][3], w3, xb1);
    }
#pragma unroll
    for (int oj = 0; oj < 4; oj++) {
        float* row = &g_WC[(long long)(k0 + to * 4 + oj) * CE + o0];
        *(u64*)&row[tt * 4]          = acc[oj][0];
        *(u64*)&row[tt * 4 + 2]      = acc[oj][1];
        *(u64*)&row[64 + tt * 4]     = acc[oj][2];
        *(u64*)&row[64 + tt * 4 + 2] = acc[oj][3];
    }
}

// ---------------- gather: quantized[b,o,t] = WC[code[b,t]][o] ----------------
__global__ __launch_bounds__(256) void k_gather(float* __restrict__ out)
{
    __shared__ __align__(16) float Tile[64 * 132];
    __shared__ int scode[128];
    int b = blockIdx.y, tid = threadIdx.x;
    long long t0 = (long long)blockIdx.x * 128;

    if (tid < 128) scode[tid] = (int)out[O_CODES + (long long)b * Tt + t0 + tid];
    __syncthreads();

    for (int oc = 0; oc < 16; oc++) {
#pragma unroll
        for (int it = 0; it < 8; it++) {
            int rr = tid + it * 256;
            int t = rr >> 4, q = rr & 15;
            float4 v = *(const float4*)&g_WC[(long long)scode[t] * CE + oc * 64 + q * 4];
            Tile[(q * 4 + 0) * 132 + t] = v.x;
            Tile[(q * 4 + 1) * 132 + t] = v.y;
            Tile[(q * 4 + 2) * 132 + t] = v.z;
            Tile[(q * 4 + 3) * 132 + t] = v.w;
        }
        __syncthreads();
#pragma unroll
        for (int it = 0; it < 8; it++) {
            int rr = tid + it * 256;
            int o = rr >> 5, t4 = rr & 31;
            *(float4*)&out[O_QUANT + (long long)b * CE * Tt + (long long)(oc * 64 + o) * Tt + t0 + t4 * 4]
                = *(const float4*)&Tile[o * 132 + t4 * 4];
        }
        __syncthreads();
    }
}

// ---------------- gemm (xproj): Out[64 x 128t] = W[64 x K] @ X[K x 128t] ----------------
__global__ __launch_bounds__(256, 2) void k_gemm64(const float* __restrict__ W, int K,
                                                   const float* __restrict__ X, long long XyS,
                                                   float* __restrict__ O, long long OyS)
{
    __shared__ __align__(16) float Ws[32][68];
    __shared__ __align__(16) float Xs[32][128];
    const float* Xp = X + (long long)blockIdx.y * XyS;
    float* Op = O + (long long)blockIdx.y * OyS + (long long)blockIdx.x * 128;
    int tid = threadIdx.x;
    int to = tid >> 4, tt = tid & 15;
    long long t0 = (long long)blockIdx.x * 128;

    u64 acc[4][4];
#pragma unroll
    for (int i = 0; i < 4; i++)
#pragma unroll
        for (int j = 0; j < 4; j++) acc[i][j] = 0ull;

    for (int kc = 0; kc < K; kc += 32) {
#pragma unroll
        for (int it = 0; it < 2; it++) {
            int rr = tid + it * 256;
            int o = rr >> 3, kq = rr & 7;
            float4 w = *(const float4*)&W[(long long)o * K + kc + kq * 4];
            Ws[kq * 4 + 0][o] = w.x; Ws[kq * 4 + 1][o] = w.y;
            Ws[kq * 4 + 2][o] = w.z; Ws[kq * 4 + 3][o] = w.w;
        }
#pragma unroll
        for (int it = 0; it < 4; it++) {
            int rr = tid + it * 256;
            int i = rr >> 5, t4 = rr & 31;
            *(float4*)&Xs[i][t4 * 4] = *(const float4*)&Xp[(long long)(kc + i) * Tt + t0 + t4 * 4];
        }
        __syncthreads();
        float4 wn  = *(const float4*)&Ws[0][to * 4];
        float4 xan = *(const float4*)&Xs[0][tt * 4];
        float4 xbn = *(const float4*)&Xs[0][64 + tt * 4];
#pragma unroll 8
        for (int k = 0; k < 32; k++) {
            float4 w = wn, xa = xan, xb = xbn;
            if (k < 31) {
                wn  = *(const float4*)&Ws[k + 1][to * 4];
                xan = *(const float4*)&Xs[k + 1][tt * 4];
                xbn = *(const float4*)&Xs[k + 1][64 + tt * 4];
            }
            u64 xa0 = pk2(xa.x, xa.y), xa1 = pk2(xa.z, xa.w);
            u64 xb0 = pk2(xb.x, xb.y), xb1 = pk2(xb.z, xb.w);
            u64 w0 = pk2(w.x, w.x), w1 = pk2(w.y, w.y), w2 = pk2(w.z, w.z), w3 = pk2(w.w, w.w);
            fma2(acc[0][0], w0, xa0); fma2(acc[0][1], w0, xa1); fma2(acc[0][2], w0, xb0); fma2(acc[0][3], w0, xb1);
            fma2(acc[1][0], w1, xa0); fma2(acc[1][1], w1, xa1); fma2(acc[1][2], w1, xb0); fma2(acc[1][3], w1, xb1);
            fma2(acc[2][0], w2, xa0); fma2(acc[2][1], w2, xa1); fma2(acc[2][2], w2, xb0); fma2(acc[2][3], w2, xb1);
            fma2(acc[3][0], w3, xa0); fma2(acc[3][1], w3, xa1); fma2(acc[3][2], w3, xb0); fma2(acc[3][3], w3, xb1);
        }
        __syncthreads();
    }
#pragma unroll
    for (int oj = 0; oj < 4; oj++) {
        long long rb = (long long)(to * 4 + oj) * Tt;
        *(u64*)&Op[rb + tt * 4]          = acc[oj][0];
        *(u64*)&Op[rb + tt * 4 + 2]      = acc[oj][1];
        *(u64*)&Op[rb + 64 + tt * 4]     = acc[oj][2];
        *(u64*)&Op[rb + 64 + tt * 4 + 2] = acc[oj][3];
    }
}

// ---------------- dist v5: R14 skeleton, fp16 single-term (K=64) ----------------
// block = 256 t, 8 warps; warp covers rows [w*16,+16) and [128+w*16,+16).
// A[t][64] fp16(e); B[k][64] fp16(-2*cb_n); 32 chunks of 128 codes, 2-stage cp.async.
// acc init = ||cb_n||^2 -> accumulator IS the (coarse) score; per-lane top-2 ->
// merge -> exact fp32 recheck of both candidates when gap < 6e-3 (60 sigma).
static constexpr int BST = 144;                       // smem row stride (conflict-free ldmatrix)
static constexpr int SM_A  = 0;                       // 256 x 144 = 36864
static constexpr int SM_B  = 36864;                   // 2 stages x 128*144 = 36864
static constexpr int SM_CC = 73728;                   // 2 x 128 floats = 1024
static constexpr int SM_DEN= 74752;                   // 256 floats
static constexpr int SM_SC = 75776;                   // 256 ints
static constexpr int SMEM_DIST = 76800;

__global__ __launch_bounds__(256, 1) void k_dist(const float* __restrict__ cb,
                                                 float* __restrict__ out)
{
    extern __shared__ __align__(1024) char smc[];
    float* ccB  = (float*)(smc + SM_CC);
    float* den  = (float*)(smc + SM_DEN);
    int*   scode= (int*)(smc + SM_SC);
    // merge scratch overlaps B (used only after the chunk loop)
    float* mv1  = (float*)(smc + SM_B);
    int*   mi1  = (int*)(smc + SM_B + 4096);
    float* mv2  = (float*)(smc + SM_B + 8192);
    int*   mi2  = (int*)(smc + SM_B + 12288);

    int b = blockIdx.y, tid = threadIdx.x;
    int wid = tid >> 5, lane = tid & 31;
    long long t0 = (long long)blockIdx.x * 256;
    const long long xbase = O_XPROJ + (long long)b * (CC * Tt) + t0;

    // ---- den from global (coalesced over t), then build fp16 A from global ----
    {
        float s = 0.f;
#pragma unroll 8
        for (int o = 0; o < 64; o++) {
            float v = out[xbase + (long long)o * Tt + tid];
            s += v * v;
        }
        den[tid] = fmaxf(__fsqrt_rn(s), 1e-12f);
    }
    __syncthreads();
#pragma unroll
    for (int it = 0; it < 64; it++) {
        int rr = tid + it * 256;                      // 16384: o = rr>>8, t = rr&255 (coalesced)
        int o = rr >> 8, t = rr & 255;
        float e = __fdiv_rn(out[xbase + (long long)o * Tt + t], den[t]);
        *(__half*)(smc + SM_A + t * BST + o * 2) = __float2half_rn(e);
    }
    __syncthreads();

    // ---- A fragments: 2 rowsets x 4 ks x 4 regs, resident ----
    u32 afr[2][4][4];
#pragma unroll
    for (int rs = 0; rs < 2; rs++) {
        int row = rs * 128 + wid * 16 + (lane & 15);
        u32 acolb = (u32)((lane >> 4) * 16);
#pragma unroll
        for (int ks = 0; ks < 4; ks++)
            ldsm4(afr[rs][ks], s2u(smc + SM_A + row * BST + ks * 32 + acolb));
    }

    const float FINF = 3.4028235e38f;
    float t1v[2][2], t2v[2][2]; int t1i[2][2], t2i[2][2];
#pragma unroll
    for (int rs = 0; rs < 2; rs++)
#pragma unroll
        for (int h = 0; h < 2; h++) {
            t1v[rs][h] = FINF; t2v[rs][h] = FINF;
            t1i[rs][h] = 0x7fffffff; t2i[rs][h] = 0x7fffffff;
        }

    auto loadB = [&](int st, int kc0) {
        char* Bd = smc + SM_B + st * (128 * BST);
        const char* gs = (const char*)g_cbF16 + (long long)kc0 * 128;
#pragma unroll
        for (int it = 0; it < 4; it++) {
            int i = tid + it * 256;                   // 1024 = 128 rows x 8 segs
            int row = i >> 3, seg = i & 7;
            cp16(s2u(Bd + row * BST + seg * 16), gs + row * 128 + seg * 16);
        }
        if (tid < 32) cp16(s2u((char*)(ccB + st * 128) + tid * 16), (const char*)(g_cbn2 + kc0) + tid * 16);
    };
    auto upd = [](float v, int kg, float& v1, int& i1, float& v2, int& i2) {
        if (v < v2) {
            if (v < v1) { v2 = v1; i2 = i1; v1 = v; i1 = kg; }
            else        { v2 = v; i2 = kg; }
        }
    };

    loadB(0, 0); cpcommit();
    for (int ch = 0; ch < 32; ch++) {
        if (ch + 1 < 32) loadB((ch + 1) & 1, (ch + 1) * 128);
        cpcommit(); cpwait1(); __syncthreads();
        const float* ccs = ccB + (ch & 1) * 128;
        char* Bd = smc + SM_B + (ch & 1) * (128 * BST);
        int kc0 = ch * 128;
        u32 brow = (u32)(lane & 7);
        u32 bselb = (u32)(((lane >> 3) & 1) * 16);
        int col = 2 * (lane & 3);

#pragma unroll
        for (int nt = 0; nt < 16; nt += 2) {
            float d[4][4];                            // [rs*2 + j][4]
#pragma unroll
            for (int j = 0; j < 2; j++) {
                int n0 = (nt + j) * 8;
                float c0 = ccs[n0 + col], c1 = ccs[n0 + col + 1];
                d[j][0] = c0; d[j][1] = c1; d[j][2] = c0; d[j][3] = c1;
                d[2 + j][0] = c0; d[2 + j][1] = c1; d[2 + j][2] = c0; d[2 + j][3] = c1;
            }
            u32 bf[4][2][2];
#pragma unroll
            for (int ks = 0; ks < 4; ks++)
#pragma unroll
                for (int j = 0; j < 2; j++)
                    ldsm2(bf[ks][j][0], bf[ks][j][1],
                          s2u(Bd + ((nt + j) * 8 + brow) * BST + ks * 32 + bselb));
#pragma unroll
            for (int ks = 0; ks < 4; ks++) {
                mma16816h(d[0], afr[0][ks], bf[ks][0]);
                mma16816h(d[1], afr[0][ks], bf[ks][1]);
                mma16816h(d[2], afr[1][ks], bf[ks][0]);
                mma16816h(d[3], afr[1][ks], bf[ks][1]);
            }
#pragma unroll
            for (int j = 0; j < 2; j++) {
                int kg = kc0 + (nt + j) * 8 + col;
                upd(d[j][0], kg,     t1v[0][0], t1i[0][0], t2v[0][0], t2i[0][0]);
                upd(d[j][1], kg + 1, t1v[0][0], t1i[0][0], t2v[0][0], t2i[0][0]);
                upd(d[j][2], kg,     t1v[0][1], t1i[0][1], t2v[0][1], t2i[0][1]);
                upd(d[j][3], kg + 1, t1v[0][1], t1i[0][1], t2v[0][1], t2i[0][1]);
                upd(d[2 + j][0], kg,     t1v[1][0], t1i[1][0], t2v[1][0], t2i[1][0]);
                upd(d[2 + j][1], kg + 1, t1v[1][0], t1i[1][0], t2v[1][0], t2i[1][0]);
                upd(d[2 + j][2], kg,     t1v[1][1], t1i[1][1], t2v[1][1], t2i[1][1]);
                upd(d[2 + j][3], kg + 1, t1v[1][1], t1i[1][1], t2v[1][1], t2i[1][1]);
            }
        }
        __syncthreads();
    }

    // ---- merge per-lane top-2 across the 4 lanes per row ----
#pragma unroll
    for (int rs = 0; rs < 2; rs++)
#pragma unroll
        for (int h = 0; h < 2; h++) {
            int row = rs * 128 + wid * 16 + h * 8 + (lane >> 2);
            int sl = lane & 3;
            mv1[row * 4 + sl] = t1v[rs][h]; mi1[row * 4 + sl] = t1i[rs][h];
            mv2[row * 4 + sl] = t2v[rs][h]; mi2[row * 4 + sl] = t2i[rs][h];
        }
    __syncthreads();
    {
        float bv1 = FINF, bv2 = FINF; int bi1 = 0x7fffffff, bi2 = 0x7fffffff;
#pragma unroll
        for (int s = 0; s < 4; s++) {
            float v = mv1[tid * 4 + s]; int i = mi1[tid * 4 + s];
            if (v < bv1 || (v == bv1 && i < bi1)) { bv2 = bv1; bi2 = bi1; bv1 = v; bi1 = i; }
            else if (v < bv2 || (v == bv2 && i < bi2)) { bv2 = v; bi2 = i; }
            v = mv2[tid * 4 + s]; i = mi2[tid * 4 + s];
            if (v < bv1 || (v == bv1 && i < bi1)) { bv2 = bv1; bi2 = bi1; bv1 = v; bi1 = i; }
            else if (v < bv2 || (v == bv2 && i < bi2)) { bv2 = v; bi2 = i; }
        }
        int code = bi1;
        if (bv2 - bv1 < 6e-3f) {                      // exact fp32 recheck of near-ties
            float dn = den[tid];
            float s1 = g_cbn2[bi1], s2 = g_cbn2[bi2];
            const float* r1 = g_cbTr + (long long)bi1 * CC;
            const float* r2 = g_cbTr + (long long)bi2 * CC;
#pragma unroll 8
            for (int o = 0; o < 64; o++) {
                float e = __fdiv_rn(out[xbase + (long long)o * Tt + tid], dn);
                s1 = fmaf(r1[o], e, s1);
                s2 = fmaf(r2[o], e, s2);
            }
            if (s2 < s1 || (s2 == s1 && bi2 < bi1)) code = bi2;
        }
        scode[tid] = code;
        out[O_CODES + (long long)b * Tt + t0 + tid] = (float)code;
    }
    __syncthreads();

    // ---- gather q, write quantized_proj = xp + (q - xp), accumulate loss ----
    {
        int code = scode[tid];
        const float* cbrow = cb + (long long)code * CC;
        long long xb2 = xbase + tid;
        long long qb2 = O_QPROJ + (long long)b * (CC * Tt) + t0 + tid;
        float ls = 0.f;
#pragma unroll 8
        for (int j = 0; j < 64; j++) {
            long long ro = (long long)j * Tt;
            float xp = out[xb2 + ro];
            float qv = cbrow[j];
            float dd = qv - xp;
            out[qb2 + ro] = xp + dd;
            ls += dd * dd;
        }
        __syncthreads();
        mv1[tid] = ls; __syncthreads();
        for (int off = 128; off > 0; off >>= 1) {
            if (tid < off) mv1[tid] += mv1[tid + off];
            __syncthreads();
        }
        if (tid == 0) g_lpart[blockIdx.y * gridDim.x + blockIdx.x] = (double)mv1[0];
    }
}

// ---------------- final loss reduction (128 partials) ----------------
__global__ __launch_bounds__(128) void k_loss(float* __restrict__ out)
{
    __shared__ double sb[128];
    int tid = threadIdx.x;
    sb[tid] = g_lpart[tid];
    __syncthreads();
    for (int off = 64; off > 0; off >>= 1) {
        if (tid < off) sb[tid] += sb[tid + off];
        __syncthreads();
    }
    if (tid == 0) {
        float l = (float)(sb[0] / (double)(16.0 * 64.0 * 2048.0));
        out[O_CBL] = l;
        out[O_CML] = l;
    }
}

extern "C" void kernel_launch(void* const* d_in, const int* in_sizes, int n_in,
                              void* d_out, int out_size) {
    (void)in_sizes; (void)n_in; (void)out_size;
    const float* x    = (const float*)d_in[0];
    const float* v_in = (const float*)d_in[1];
    const float* g_in = (const float*)d_in[2];
    const float* v_out= (const float*)d_in[3];
    const float* g_out= (const float*)d_in[4];
    const float* cb   = (const float*)d_in[5];
    float* out = (float*)d_out;

    cudaFuncSetAttribute(k_dist, cudaFuncAttributeMaxDynamicSharedMemorySize, SMEM_DIST);

    k_prep_win<<<64, 256>>>(v_in, g_in);
    k_prep_wout<<<128, 256>>>(v_out, g_out);
    k_prep_cb<<<512, 256>>>(cb);

    float* winp; cudaGetSymbolAddress((void**)&winp, g_Win);

    // WC = codebook @ W_out^T
    k_wc<<<dim3(64, 8), 256>>>(cb);

    // x_proj = W_in @ x
    k_gemm64<<<dim3(16, 16), 256>>>(winp, CE, x, (long long)CE * Tt,
                                    out + O_XPROJ, (long long)CC * Tt);

    // codes / qproj / loss partials (fp16 tensor-core dist, R14 skeleton)
    k_dist<<<dim3(8, 16), 256, SMEM_DIST>>>(cb, out);
    k_loss<<<1, 128>>>(out);

    // quantized via gather from WC
    k_gather<<<dim3(16, 16), 256>>>(out);
}